// round 1
// baseline (speedup 1.0000x reference)
#include <cuda_runtime.h>
#include <math_constants.h>
#include <math.h>

#define BATCH 2
#define SEQ   2048
#define HID   4096
#define NH    32
#define HDIM  128
#define QKVN  (3*HID)

// Scratch (device globals: allocation-guard safe)
__device__ float g_qkv[(size_t)BATCH * SEQ * QKVN];   // (B,S,3H) : q|k|v
__device__ float g_attn[(size_t)BATCH * SEQ * HID];   // (B,S,H)

// ---------------------------------------------------------------------------
// SGEMM: C[M,N] = A[M,K] @ B[K,N], all row-major. 128x128x8 block, 8x8/thread.
// ---------------------------------------------------------------------------
template<int M, int N, int K>
__device__ __forceinline__ void sgemm_body(const float* __restrict__ A,
                                           const float* __restrict__ Bm,
                                           float* __restrict__ C) {
    constexpr int BM = 128, BN = 128, BK = 8;
    __shared__ float As[BK][BM];   // A transposed: As[k][m]
    __shared__ float Bs[BK][BN];

    const int tid  = threadIdx.x;          // 256 threads
    const int row0 = blockIdx.y * BM;
    const int col0 = blockIdx.x * BN;
    const int tr   = tid >> 4;             // 0..15  -> rows tr*8..tr*8+7
    const int tc   = tid & 15;             // 0..15  -> cols tc*8..tc*8+7

    const int aRow = tid >> 1;             // 0..127
    const int aCol = (tid & 1) << 2;       // 0 or 4
    const int bRow = tid >> 5;             // 0..7
    const int bCol = (tid & 31) << 2;      // 0..124

    float acc[8][8];
#pragma unroll
    for (int i = 0; i < 8; i++)
#pragma unroll
        for (int j = 0; j < 8; j++) acc[i][j] = 0.f;

    const float* Aptr = A  + (size_t)(row0 + aRow) * K + aCol;
    const float* Bptr = Bm + (size_t)bRow * N + col0 + bCol;

    for (int k0 = 0; k0 < K; k0 += BK) {
        float4 a = *(const float4*)(Aptr + k0);
        As[aCol + 0][aRow] = a.x;
        As[aCol + 1][aRow] = a.y;
        As[aCol + 2][aRow] = a.z;
        As[aCol + 3][aRow] = a.w;
        *(float4*)(&Bs[bRow][bCol]) = *(const float4*)(Bptr + (size_t)k0 * N);
        __syncthreads();

#pragma unroll
        for (int kk = 0; kk < BK; kk++) {
            float ra[8], rb[8];
            *(float4*)(ra)     = *(const float4*)(&As[kk][tr * 8]);
            *(float4*)(ra + 4) = *(const float4*)(&As[kk][tr * 8 + 4]);
            *(float4*)(rb)     = *(const float4*)(&Bs[kk][tc * 8]);
            *(float4*)(rb + 4) = *(const float4*)(&Bs[kk][tc * 8 + 4]);
#pragma unroll
            for (int i = 0; i < 8; i++)
#pragma unroll
                for (int j = 0; j < 8; j++)
                    acc[i][j] = fmaf(ra[i], rb[j], acc[i][j]);
        }
        __syncthreads();
    }

#pragma unroll
    for (int i = 0; i < 8; i++) {
        float* cp = C + (size_t)(row0 + tr * 8 + i) * N + col0 + tc * 8;
        *(float4*)(cp)     = make_float4(acc[i][0], acc[i][1], acc[i][2], acc[i][3]);
        *(float4*)(cp + 4) = make_float4(acc[i][4], acc[i][5], acc[i][6], acc[i][7]);
    }
}

__global__ __launch_bounds__(256) void gemm_qkv_kernel(const float* __restrict__ A,
                                                       const float* __restrict__ W) {
    sgemm_body<BATCH * SEQ, QKVN, HID>(A, W, g_qkv);
}

__global__ __launch_bounds__(256) void gemm_out_kernel(const float* __restrict__ W,
                                                       float* __restrict__ C) {
    sgemm_body<BATCH * SEQ, HID, HID>(g_attn, W, C);
}

// ---------------------------------------------------------------------------
// NeoX RoPE in-place on q and k of g_qkv. One thread per (b,s,h,j), j in [0,32)
// ---------------------------------------------------------------------------
__global__ void rope_kernel(const int* __restrict__ positions) {
    int idx = blockIdx.x * blockDim.x + threadIdx.x;
    int j  = idx & 31;
    int h  = (idx >> 5) & 31;
    int bs = idx >> 10;                    // 0 .. BATCH*SEQ-1

    float pos = (float)positions[bs];
    float inv = powf(10000.0f, -(float)j * (1.0f / 32.0f));
    float ang = pos * inv;
    float sn, cs;
    sincosf(ang, &sn, &cs);

    size_t base = (size_t)bs * QKVN + (size_t)h * HDIM;
    // q
    float x1 = g_qkv[base + j], x2 = g_qkv[base + 32 + j];
    g_qkv[base + j]      = x1 * cs - x2 * sn;
    g_qkv[base + 32 + j] = x2 * cs + x1 * sn;
    // k
    size_t kb = base + HID;
    x1 = g_qkv[kb + j]; x2 = g_qkv[kb + 32 + j];
    g_qkv[kb + j]      = x1 * cs - x2 * sn;
    g_qkv[kb + 32 + j] = x2 * cs + x1 * sn;
}

// ---------------------------------------------------------------------------
// Flash attention, fp32, causal. Block = (q-tile of 64) x (one b,h). 256 thr.
// ---------------------------------------------------------------------------
#define BQ  64
#define BK2 64

struct FlashSmem {
    float Qt[HDIM][BQ + 4];    // Q transposed (k-major), stride 68 (16B-aligned rows of 4)
    float Kt[HDIM][BK2 + 4];   // K transposed
    float Vs[BK2][HDIM];       // V natural (key-major) = k-major for PV
    float St[BK2][BQ + 4];     // scores/probs transposed: St[key][query]
    float m_s[BQ];
    float l_s[BQ];
    float a_s[BQ];
};

__global__ __launch_bounds__(256, 1) void flash_kernel() {
    extern __shared__ char smraw[];
    FlashSmem& sm = *reinterpret_cast<FlashSmem*>(smraw);

    const int tid = threadIdx.x;
    const int qt  = blockIdx.x;            // q tile
    const int b   = blockIdx.y >> 5;
    const int h   = blockIdx.y & 31;
    const float scale = 0.08838834764831845f;  // 1/sqrt(128)

    const int tr = tid >> 4;               // 0..15 -> rows tr*4..tr*4+3
    const int tc = tid & 15;               // 0..15 -> QK cols tc*4.. / PV cols tc*8..

    // ---- load Q tile, transposed + pre-scaled ----
    {
        size_t qbase = (size_t)(b * SEQ + qt * BQ) * QKVN + h * HDIM;
        for (int it = tid; it < (BQ / 4) * HDIM; it += 256) {
            int d  = it & (HDIM - 1);      // consecutive lanes -> consecutive d (coalesced)
            int rg = it >> 7;              // 0..15 row-group
            const float* p = &g_qkv[qbase + (size_t)(rg * 4) * QKVN + d];
            *(float4*)(&sm.Qt[d][rg * 4]) =
                make_float4(p[0] * scale, p[QKVN] * scale,
                            p[2 * (size_t)QKVN] * scale, p[3 * (size_t)QKVN] * scale);
        }
    }
    if (tid < BQ) { sm.m_s[tid] = -CUDART_INF_F; sm.l_s[tid] = 0.f; }

    float acc[4][8];
#pragma unroll
    for (int i = 0; i < 4; i++)
#pragma unroll
        for (int j = 0; j < 8; j++) acc[i][j] = 0.f;

    for (int kt = 0; kt <= qt; kt++) {
        size_t kbase = (size_t)(b * SEQ + kt * BK2) * QKVN + HID + h * HDIM;
        size_t vbase = kbase + HID;

        // K transposed
        for (int it = tid; it < (BK2 / 4) * HDIM; it += 256) {
            int d  = it & (HDIM - 1);
            int rg = it >> 7;
            const float* p = &g_qkv[kbase + (size_t)(rg * 4) * QKVN + d];
            *(float4*)(&sm.Kt[d][rg * 4]) =
                make_float4(p[0], p[QKVN], p[2 * (size_t)QKVN], p[3 * (size_t)QKVN]);
        }
        // V natural
        for (int it = tid; it < BK2 * HDIM / 4; it += 256) {
            int r  = it >> 5;
            int c4 = (it & 31) << 2;
            *(float4*)(&sm.Vs[r][c4]) =
                *(const float4*)(&g_qkv[vbase + (size_t)r * QKVN + c4]);
        }
        __syncthreads();

        // ---- S = Q K^T (4x4 micro-tile) ----
        float s[4][4];
#pragma unroll
        for (int i = 0; i < 4; i++)
#pragma unroll
            for (int j = 0; j < 4; j++) s[i][j] = 0.f;

#pragma unroll 4
        for (int kk = 0; kk < HDIM; kk++) {
            float rq[4], rk[4];
            *(float4*)rq = *(const float4*)(&sm.Qt[kk][tr * 4]);
            *(float4*)rk = *(const float4*)(&sm.Kt[kk][tc * 4]);
#pragma unroll
            for (int i = 0; i < 4; i++)
#pragma unroll
                for (int j = 0; j < 4; j++)
                    s[i][j] = fmaf(rq[i], rk[j], s[i][j]);
        }

        if (kt == qt) {                     // diagonal tile: causal mask
#pragma unroll
            for (int i = 0; i < 4; i++)
#pragma unroll
                for (int j = 0; j < 4; j++)
                    if (tc * 4 + j > tr * 4 + i) s[i][j] = -CUDART_INF_F;
        }

        // store transposed: St[key][query], vectorized along query
#pragma unroll
        for (int j = 0; j < 4; j++)
            *(float4*)(&sm.St[tc * 4 + j][tr * 4]) =
                make_float4(s[0][j], s[1][j], s[2][j], s[3][j]);
        __syncthreads();

        // ---- online softmax: 4 threads per query row ----
        {
            int r = tid >> 2, p = tid & 3;
            float mloc = -CUDART_INF_F;
#pragma unroll
            for (int cc = 0; cc < 16; cc++)
                mloc = fmaxf(mloc, sm.St[p * 16 + cc][r]);
            mloc = fmaxf(mloc, __shfl_xor_sync(0xffffffffu, mloc, 1));
            mloc = fmaxf(mloc, __shfl_xor_sync(0xffffffffu, mloc, 2));
            float mold = sm.m_s[r];
            float mnew = fmaxf(mold, mloc);
            float sum = 0.f;
#pragma unroll
            for (int cc = 0; cc < 16; cc++) {
                float e = __expf(sm.St[p * 16 + cc][r] - mnew);
                sm.St[p * 16 + cc][r] = e;
                sum += e;
            }
            sum += __shfl_xor_sync(0xffffffffu, sum, 1);
            sum += __shfl_xor_sync(0xffffffffu, sum, 2);
            if (p == 0) {
                float alpha = __expf(mold - mnew);
                sm.a_s[r] = alpha;
                sm.l_s[r] = alpha * sm.l_s[r] + sum;
                sm.m_s[r] = mnew;
            }
        }
        __syncthreads();

        // ---- O = alpha*O + P V (4x8 micro-tile) ----
        float al[4];
#pragma unroll
        for (int i = 0; i < 4; i++) al[i] = sm.a_s[tr * 4 + i];
#pragma unroll
        for (int i = 0; i < 4; i++)
#pragma unroll
            for (int j = 0; j < 8; j++) acc[i][j] *= al[i];

#pragma unroll 2
        for (int kk = 0; kk < BK2; kk++) {
            float rp[4], rv[8];
            *(float4*)rp       = *(const float4*)(&sm.St[kk][tr * 4]);
            *(float4*)rv       = *(const float4*)(&sm.Vs[kk][tc * 8]);
            *(float4*)(rv + 4) = *(const float4*)(&sm.Vs[kk][tc * 8 + 4]);
#pragma unroll
            for (int i = 0; i < 4; i++)
#pragma unroll
                for (int j = 0; j < 8; j++)
                    acc[i][j] = fmaf(rp[i], rv[j], acc[i][j]);
        }
        __syncthreads();   // protect Kt/Vs/St before next tile
    }

    // ---- epilogue: O / l -> g_attn ----
#pragma unroll
    for (int i = 0; i < 4; i++) {
        int r = tr * 4 + i;
        float invl = 1.0f / sm.l_s[r];
        size_t ob = (size_t)(b * SEQ + qt * BQ + r) * HID + h * HDIM + tc * 8;
        *(float4*)(&g_attn[ob]) =
            make_float4(acc[i][0] * invl, acc[i][1] * invl, acc[i][2] * invl, acc[i][3] * invl);
        *(float4*)(&g_attn[ob + 4]) =
            make_float4(acc[i][4] * invl, acc[i][5] * invl, acc[i][6] * invl, acc[i][7] * invl);
    }
}

// ---------------------------------------------------------------------------
extern "C" void kernel_launch(void* const* d_in, const int* in_sizes, int n_in,
                              void* d_out, int out_size) {
    const float* hidden    = (const float*)d_in[0];   // (B,S,H) fp32
    const int*   positions = (const int*)d_in[1];     // (B,S) int32
    const float* Wqkv      = (const float*)d_in[2];   // (H,3H) fp32
    const float* Wout      = (const float*)d_in[3];   // (H,H) fp32
    float*       out       = (float*)d_out;           // (B,S,H) fp32

    // 1) QKV projection
    gemm_qkv_kernel<<<dim3(QKVN / 128, (BATCH * SEQ) / 128), 256>>>(hidden, Wqkv);

    // 2) RoPE (q,k in-place)
    rope_kernel<<<(BATCH * SEQ * NH * 32) / 256, 256>>>(positions);

    // 3) Causal flash attention
    cudaFuncSetAttribute(flash_kernel, cudaFuncAttributeMaxDynamicSharedMemorySize,
                         (int)sizeof(FlashSmem));
    flash_kernel<<<dim3(SEQ / BQ, BATCH * NH), 256, sizeof(FlashSmem)>>>();

    // 4) Output projection
    gemm_out_kernel<<<dim3(HID / 128, (BATCH * SEQ) / 128), 256>>>(Wout, out);
}

// round 3
// speedup vs baseline: 2.2711x; 2.2711x over previous
#include <cuda_runtime.h>
#include <cuda_bf16.h>
#include <math_constants.h>
#include <math.h>
#include <cstdint>

#define BATCH 2
#define SEQ   2048
#define HID   4096
#define NH    32
#define HDIM  128
#define QKVN  (3*HID)
#define MROWS (BATCH*SEQ)      // 4096
#define KSPLIT (3*HID)         // 12288 : split-concatenated K

// ---------------- scratch (device globals: allocation-guard safe) ----------
__device__ float         g_qkv [(size_t)MROWS * QKVN];    // 200MB
__device__ float         g_attn[(size_t)MROWS * HID];     // 64MB
__device__ __nv_bfloat16 g_A2  [(size_t)MROWS * KSPLIT];  // 96MB  [Ahi|Ahi|Alo]
__device__ __nv_bfloat16 g_B2  [(size_t)QKVN  * KSPLIT];  // 288MB [Bhi|Blo|Bhi] (N-major)

// ---------------- small PTX helpers (all sm_80-era, compute_103-safe) ------
__device__ __forceinline__ uint32_t smem_u32(const void* p) {
    uint32_t a;
    asm("{ .reg .u64 t; cvta.to.shared.u64 t, %1; cvt.u32.u64 %0, t; }" : "=r"(a) : "l"(p));
    return a;
}
__device__ __forceinline__ void cp16(uint32_t s, const void* g) {
    asm volatile("cp.async.cg.shared.global [%0], [%1], 16;" :: "r"(s), "l"(g) : "memory");
}
__device__ __forceinline__ void ldsm4(uint32_t* r, uint32_t addr) {
    asm volatile("ldmatrix.sync.aligned.m8n8.x4.shared.b16 {%0,%1,%2,%3}, [%4];"
                 : "=r"(r[0]), "=r"(r[1]), "=r"(r[2]), "=r"(r[3]) : "r"(addr));
}
__device__ __forceinline__ void mma_bf16(float* d, const uint32_t* a, uint32_t b0, uint32_t b1) {
    asm volatile("mma.sync.aligned.m16n8k16.row.col.f32.bf16.bf16.f32 "
                 "{%0,%1,%2,%3}, {%4,%5,%6,%7}, {%8,%9}, {%0,%1,%2,%3};"
                 : "+f"(d[0]), "+f"(d[1]), "+f"(d[2]), "+f"(d[3])
                 : "r"(a[0]), "r"(a[1]), "r"(a[2]), "r"(a[3]), "r"(b0), "r"(b1));
}

struct alignas(8) bh4 { __nv_bfloat16 h[4]; };

// ============================================================================
// Split prepass 1: activations  src fp32 [M][4096] -> dst bf16 [M][12288]
//   dst[m][k]=hi, dst[m][4096+k]=hi, dst[m][8192+k]=lo
// ============================================================================
__global__ __launch_bounds__(256) void split_act_kernel(const float* __restrict__ src,
                                                        __nv_bfloat16* __restrict__ dst) {
    size_t i = (size_t)blockIdx.x * 256 + threadIdx.x;   // over M*1024 float4s
    int row = (int)(i >> 10);
    int kc  = (int)(i & 1023);
    float4 v = ((const float4*)src)[i];
    bh4 hi, lo;
    hi.h[0] = __float2bfloat16(v.x); lo.h[0] = __float2bfloat16(v.x - __bfloat162float(hi.h[0]));
    hi.h[1] = __float2bfloat16(v.y); lo.h[1] = __float2bfloat16(v.y - __bfloat162float(hi.h[1]));
    hi.h[2] = __float2bfloat16(v.z); lo.h[2] = __float2bfloat16(v.z - __bfloat162float(hi.h[2]));
    hi.h[3] = __float2bfloat16(v.w); lo.h[3] = __float2bfloat16(v.w - __bfloat162float(hi.h[3]));
    __nv_bfloat16* d = dst + (size_t)row * KSPLIT + kc * 4;
    *(bh4*)(d)        = hi;
    *(bh4*)(d + 4096) = hi;
    *(bh4*)(d + 8192) = lo;
}

// ============================================================================
// Split prepass 2: weights  src fp32 [K=4096][N] (row-major) -> dst bf16 [N][12288]
//   dst[n][k]=hi, dst[n][4096+k]=lo, dst[n][8192+k]=hi   (fused transpose)
// ============================================================================
__global__ __launch_bounds__(256) void split_w_kernel(const float* __restrict__ src,
                                                      __nv_bfloat16* __restrict__ dst,
                                                      int N) {
    __shared__ float t[32][33];
    int n0 = blockIdx.x * 32, k0 = blockIdx.y * 32;
    int tx = threadIdx.x & 31, ty = threadIdx.x >> 5;    // (32 x 8)
#pragma unroll
    for (int i = 0; i < 4; i++)
        t[ty + i * 8][tx] = src[(size_t)(k0 + ty + i * 8) * N + n0 + tx];
    __syncthreads();
#pragma unroll
    for (int i = 0; i < 4; i++) {
        int n = n0 + ty + i * 8;
        int k = k0 + tx;
        float x = t[tx][ty + i * 8];
        __nv_bfloat16 hi = __float2bfloat16(x);
        __nv_bfloat16 lo = __float2bfloat16(x - __bfloat162float(hi));
        __nv_bfloat16* d = dst + (size_t)n * KSPLIT;
        d[k]        = hi;
        d[4096 + k] = lo;
        d[8192 + k] = hi;
    }
}

// ============================================================================
// bf16 tensor-core GEMM: C[M][N] = A2[M][12288] @ B2[N][12288]^T (fp32 accum)
// 128x128x32 tile, 256 thr (4x2 warps, 32x64 warp tile), 4-stage cp.async.
// ============================================================================
#define GSTAGES   4
#define GROW_B    80                     // bytes per smem row (32 bf16 + 8 pad)
#define GTILE_B   (128 * GROW_B)         // 10240 per operand
#define GSTAGE_B  (2 * GTILE_B)          // 20480
#define GSMEM_B   (GSTAGES * GSTAGE_B)   // 81920

__global__ __launch_bounds__(256, 2) void gemm_bf16_kernel(const __nv_bfloat16* __restrict__ A,
                                                           const __nv_bfloat16* __restrict__ B,
                                                           float* __restrict__ C, int N) {
    extern __shared__ char sm[];
    const int KT  = KSPLIT;              // 12288
    const int NT  = KT / 32;             // 384 k-iterations
    const int tid  = threadIdx.x;
    const int lane = tid & 31;
    const int wid  = tid >> 5;
    const int wm   = wid & 3;            // 4 warps along M (32 rows each)
    const int wn   = wid >> 2;           // 2 warps along N (64 cols each)

    // band rasterization: 8 M-tiles per band for B-panel L2 reuse
    const int tiles_n = N >> 7;
    int bid  = blockIdx.x + blockIdx.y * gridDim.x;
    int band = bid / (8 * tiles_n);
    int rem  = bid % (8 * tiles_n);
    const int mt = band * 8 + (rem & 7);
    const int nt = rem >> 3;
    const int row0 = mt * 128, col0 = nt * 128;

    const __nv_bfloat16* Ab = A + (size_t)row0 * KT;
    const __nv_bfloat16* Bb = B + (size_t)col0 * KT;
    const uint32_t smb = smem_u32(sm);

    auto load_stage = [&](int s, int kt) {
        uint32_t sA = smb + s * GSTAGE_B;
        const __nv_bfloat16* ga = Ab + kt * 32;
        const __nv_bfloat16* gb = Bb + kt * 32;
#pragma unroll
        for (int i = 0; i < 2; i++) {
            int c   = tid + i * 256;     // 512 16B-chunks per operand
            int row = c >> 2;
            int kc  = c & 3;
            cp16(sA + row * GROW_B + kc * 16,            ga + (size_t)row * KT + kc * 8);
            cp16(sA + GTILE_B + row * GROW_B + kc * 16,  gb + (size_t)row * KT + kc * 8);
        }
    };

    load_stage(0, 0); asm volatile("cp.async.commit_group;" ::: "memory");
    load_stage(1, 1); asm volatile("cp.async.commit_group;" ::: "memory");
    load_stage(2, 2); asm volatile("cp.async.commit_group;" ::: "memory");

    float acc[2][8][4];
#pragma unroll
    for (int i = 0; i < 2; i++)
#pragma unroll
        for (int j = 0; j < 8; j++)
#pragma unroll
            for (int q = 0; q < 4; q++) acc[i][j][q] = 0.f;

    // ldmatrix lane geometry
    const int a_row = lane & 15;
    const int a_col = (lane >> 4) * 8;
    const int b_nl  = (lane & 7) + ((lane >> 4) & 1) * 8;
    const int b_kl  = ((lane >> 3) & 1) * 8;

    for (int kt = 0; kt < NT; kt++) {
        asm volatile("cp.async.wait_group 2;" ::: "memory");
        __syncthreads();
        const int s = kt & 3;
        const uint32_t aB = smb + s * GSTAGE_B;
        const uint32_t bB = aB + GTILE_B;

#pragma unroll
        for (int ks = 0; ks < 2; ks++) {
            uint32_t afrag[2][4];
#pragma unroll
            for (int mf = 0; mf < 2; mf++)
                ldsm4(afrag[mf], aB + (uint32_t)((wm * 32 + mf * 16 + a_row) * GROW_B
                                                 + (ks * 16 + a_col) * 2));
#pragma unroll
            for (int nf2 = 0; nf2 < 4; nf2++) {
                uint32_t bfrag[4];
                ldsm4(bfrag, bB + (uint32_t)((wn * 64 + nf2 * 16 + b_nl) * GROW_B
                                             + (ks * 16 + b_kl) * 2));
#pragma unroll
                for (int mf = 0; mf < 2; mf++) {
                    mma_bf16(acc[mf][nf2 * 2],     afrag[mf], bfrag[0], bfrag[1]);
                    mma_bf16(acc[mf][nf2 * 2 + 1], afrag[mf], bfrag[2], bfrag[3]);
                }
            }
        }
        if (kt + 3 < NT) load_stage((kt + 3) & 3, kt + 3);
        asm volatile("cp.async.commit_group;" ::: "memory");
    }

    // epilogue
#pragma unroll
    for (int mf = 0; mf < 2; mf++)
#pragma unroll
        for (int nf = 0; nf < 8; nf++) {
            int r  = row0 + wm * 32 + mf * 16 + (lane >> 2);
            int cc = col0 + wn * 64 + nf * 8 + (lane & 3) * 2;
            *(float2*)&C[(size_t)r * N + cc]       = make_float2(acc[mf][nf][0], acc[mf][nf][1]);
            *(float2*)&C[(size_t)(r + 8) * N + cc] = make_float2(acc[mf][nf][2], acc[mf][nf][3]);
        }
}

// ============================================================================
// NeoX RoPE in-place on q and k of g_qkv.
// ============================================================================
__global__ void rope_kernel(const int* __restrict__ positions) {
    int idx = blockIdx.x * blockDim.x + threadIdx.x;
    int j  = idx & 31;
    int h  = (idx >> 5) & 31;
    int bs = idx >> 10;

    float pos = (float)positions[bs];
    float inv = powf(10000.0f, -(float)j * (1.0f / 32.0f));
    float sn, cs;
    sincosf(pos * inv, &sn, &cs);

    size_t base = (size_t)bs * QKVN + (size_t)h * HDIM;
    float x1 = g_qkv[base + j], x2 = g_qkv[base + 32 + j];
    g_qkv[base + j]      = x1 * cs - x2 * sn;
    g_qkv[base + 32 + j] = x2 * cs + x1 * sn;
    size_t kb = base + HID;
    x1 = g_qkv[kb + j]; x2 = g_qkv[kb + 32 + j];
    g_qkv[kb + j]      = x1 * cs - x2 * sn;
    g_qkv[kb + 32 + j] = x2 * cs + x1 * sn;
}

// ============================================================================
// Flash attention, fp32, causal (unchanged from R1 passing version)
// ============================================================================
#define BQ  64
#define BK2 64
struct FlashSmem {
    float Qt[HDIM][BQ + 4];
    float Kt[HDIM][BK2 + 4];
    float Vs[BK2][HDIM];
    float St[BK2][BQ + 4];
    float m_s[BQ];
    float l_s[BQ];
    float a_s[BQ];
};

__global__ __launch_bounds__(256, 1) void flash_kernel() {
    extern __shared__ char smraw[];
    FlashSmem& sm = *reinterpret_cast<FlashSmem*>(smraw);

    const int tid = threadIdx.x;
    const int qt  = blockIdx.x;
    const int b   = blockIdx.y >> 5;
    const int h   = blockIdx.y & 31;
    const float scale = 0.08838834764831845f;

    const int tr = tid >> 4;
    const int tc = tid & 15;

    {
        size_t qbase = (size_t)(b * SEQ + qt * BQ) * QKVN + h * HDIM;
        for (int it = tid; it < (BQ / 4) * HDIM; it += 256) {
            int d  = it & (HDIM - 1);
            int rg = it >> 7;
            const float* p = &g_qkv[qbase + (size_t)(rg * 4) * QKVN + d];
            *(float4*)(&sm.Qt[d][rg * 4]) =
                make_float4(p[0] * scale, p[QKVN] * scale,
                            p[2 * (size_t)QKVN] * scale, p[3 * (size_t)QKVN] * scale);
        }
    }
    if (tid < BQ) { sm.m_s[tid] = -CUDART_INF_F; sm.l_s[tid] = 0.f; }

    float acc[4][8];
#pragma unroll
    for (int i = 0; i < 4; i++)
#pragma unroll
        for (int j = 0; j < 8; j++) acc[i][j] = 0.f;

    for (int kt = 0; kt <= qt; kt++) {
        size_t kbase = (size_t)(b * SEQ + kt * BK2) * QKVN + HID + h * HDIM;
        size_t vbase = kbase + HID;

        for (int it = tid; it < (BK2 / 4) * HDIM; it += 256) {
            int d  = it & (HDIM - 1);
            int rg = it >> 7;
            const float* p = &g_qkv[kbase + (size_t)(rg * 4) * QKVN + d];
            *(float4*)(&sm.Kt[d][rg * 4]) =
                make_float4(p[0], p[QKVN], p[2 * (size_t)QKVN], p[3 * (size_t)QKVN]);
        }
        for (int it = tid; it < BK2 * HDIM / 4; it += 256) {
            int r  = it >> 5;
            int c4 = (it & 31) << 2;
            *(float4*)(&sm.Vs[r][c4]) =
                *(const float4*)(&g_qkv[vbase + (size_t)r * QKVN + c4]);
        }
        __syncthreads();

        float s[4][4];
#pragma unroll
        for (int i = 0; i < 4; i++)
#pragma unroll
            for (int j = 0; j < 4; j++) s[i][j] = 0.f;

#pragma unroll 4
        for (int kk = 0; kk < HDIM; kk++) {
            float rq[4], rk[4];
            *(float4*)rq = *(const float4*)(&sm.Qt[kk][tr * 4]);
            *(float4*)rk = *(const float4*)(&sm.Kt[kk][tc * 4]);
#pragma unroll
            for (int i = 0; i < 4; i++)
#pragma unroll
                for (int j = 0; j < 4; j++)
                    s[i][j] = fmaf(rq[i], rk[j], s[i][j]);
        }

        if (kt == qt) {
#pragma unroll
            for (int i = 0; i < 4; i++)
#pragma unroll
                for (int j = 0; j < 4; j++)
                    if (tc * 4 + j > tr * 4 + i) s[i][j] = -CUDART_INF_F;
        }

#pragma unroll
        for (int j = 0; j < 4; j++)
            *(float4*)(&sm.St[tc * 4 + j][tr * 4]) =
                make_float4(s[0][j], s[1][j], s[2][j], s[3][j]);
        __syncthreads();

        {
            int rr = tid >> 2, p = tid & 3;
            float mloc = -CUDART_INF_F;
#pragma unroll
            for (int cc = 0; cc < 16; cc++)
                mloc = fmaxf(mloc, sm.St[p * 16 + cc][rr]);
            mloc = fmaxf(mloc, __shfl_xor_sync(0xffffffffu, mloc, 1));
            mloc = fmaxf(mloc, __shfl_xor_sync(0xffffffffu, mloc, 2));
            float mold = sm.m_s[rr];
            float mnew = fmaxf(mold, mloc);
            float sum = 0.f;
#pragma unroll
            for (int cc = 0; cc < 16; cc++) {
                float e = __expf(sm.St[p * 16 + cc][rr] - mnew);
                sm.St[p * 16 + cc][rr] = e;
                sum += e;
            }
            sum += __shfl_xor_sync(0xffffffffu, sum, 1);
            sum += __shfl_xor_sync(0xffffffffu, sum, 2);
            if (p == 0) {
                float alpha = __expf(mold - mnew);
                sm.a_s[rr] = alpha;
                sm.l_s[rr] = alpha * sm.l_s[rr] + sum;
                sm.m_s[rr] = mnew;
            }
        }
        __syncthreads();

        float al[4];
#pragma unroll
        for (int i = 0; i < 4; i++) al[i] = sm.a_s[tr * 4 + i];
#pragma unroll
        for (int i = 0; i < 4; i++)
#pragma unroll
            for (int j = 0; j < 8; j++) acc[i][j] *= al[i];

#pragma unroll 2
        for (int kk = 0; kk < BK2; kk++) {
            float rp[4], rv[8];
            *(float4*)rp       = *(const float4*)(&sm.St[kk][tr * 4]);
            *(float4*)rv       = *(const float4*)(&sm.Vs[kk][tc * 8]);
            *(float4*)(rv + 4) = *(const float4*)(&sm.Vs[kk][tc * 8 + 4]);
#pragma unroll
            for (int i = 0; i < 4; i++)
#pragma unroll
                for (int j = 0; j < 8; j++)
                    acc[i][j] = fmaf(rp[i], rv[j], acc[i][j]);
        }
        __syncthreads();
    }

#pragma unroll
    for (int i = 0; i < 4; i++) {
        int rr = tr * 4 + i;
        float invl = 1.0f / sm.l_s[rr];
        size_t ob = (size_t)(b * SEQ + qt * BQ + rr) * HID + h * HDIM + tc * 8;
        *(float4*)(&g_attn[ob]) =
            make_float4(acc[i][0] * invl, acc[i][1] * invl, acc[i][2] * invl, acc[i][3] * invl);
        *(float4*)(&g_attn[ob + 4]) =
            make_float4(acc[i][4] * invl, acc[i][5] * invl, acc[i][6] * invl, acc[i][7] * invl);
    }
}

// ============================================================================
extern "C" void kernel_launch(void* const* d_in, const int* in_sizes, int n_in,
                              void* d_out, int out_size) {
    const float* hidden    = (const float*)d_in[0];
    const int*   positions = (const int*)d_in[1];
    const float* Wqkv      = (const float*)d_in[2];   // (H, 3H)
    const float* Wout      = (const float*)d_in[3];   // (H, H)
    float*       out       = (float*)d_out;

    float*         qkv;  cudaGetSymbolAddress((void**)&qkv,  g_qkv);
    float*         attn; cudaGetSymbolAddress((void**)&attn, g_attn);
    __nv_bfloat16* A2;   cudaGetSymbolAddress((void**)&A2,   g_A2);
    __nv_bfloat16* B2;   cudaGetSymbolAddress((void**)&B2,   g_B2);

    static bool attr_done = false;
    if (!attr_done) {
        cudaFuncSetAttribute(gemm_bf16_kernel, cudaFuncAttributeMaxDynamicSharedMemorySize, GSMEM_B);
        cudaFuncSetAttribute(flash_kernel, cudaFuncAttributeMaxDynamicSharedMemorySize,
                             (int)sizeof(FlashSmem));
        attr_done = true;
    }

    // 1) split activations + weights into concatenated bf16 hi/lo form
    split_act_kernel<<<(MROWS * (HID / 4)) / 256, 256>>>(hidden, A2);
    split_w_kernel<<<dim3(QKVN / 32, HID / 32), 256>>>(Wqkv, B2, QKVN);

    // 2) QKV projection on tensor cores (exact fp32 via 3-term split)
    gemm_bf16_kernel<<<dim3(QKVN / 128, MROWS / 128), 256, GSMEM_B>>>(A2, B2, qkv, QKVN);

    // 3) RoPE
    rope_kernel<<<(MROWS * NH * 32) / 256, 256>>>(positions);

    // 4) Causal flash attention
    flash_kernel<<<dim3(SEQ / BQ, BATCH * NH), 256, sizeof(FlashSmem)>>>();

    // 5) split attn output + Wout, then output projection
    split_act_kernel<<<(MROWS * (HID / 4)) / 256, 256>>>(attn, A2);
    split_w_kernel<<<dim3(HID / 32, HID / 32), 256>>>(Wout, B2, HID);
    gemm_bf16_kernel<<<dim3(HID / 128, MROWS / 128), 256, GSMEM_B>>>(A2, B2, out, HID);
}

// round 4
// speedup vs baseline: 3.2401x; 1.4267x over previous
#include <cuda_runtime.h>
#include <cuda_bf16.h>
#include <math_constants.h>
#include <math.h>
#include <cstdint>

#define BATCH 2
#define SEQ   2048
#define HID   4096
#define NH    32
#define HDIM  128
#define QKVN  (3*HID)
#define MROWS (BATCH*SEQ)      // 4096
#define KSPLIT (3*HID)         // 12288 : split-concatenated K

// ---------------- scratch (device globals: allocation-guard safe) ----------
__device__ float         g_qkv [(size_t)MROWS * QKVN];
__device__ float         g_attn[(size_t)MROWS * HID];
__device__ __nv_bfloat16 g_A2  [(size_t)MROWS * KSPLIT];
__device__ __nv_bfloat16 g_B2  [(size_t)QKVN  * KSPLIT];
// flash operands: [bh][s][d] for q,k ; [bh][d][s] for v (transposed)
__device__ __nv_bfloat16 g_qhi[(size_t)BATCH * NH * SEQ * HDIM];
__device__ __nv_bfloat16 g_qlo[(size_t)BATCH * NH * SEQ * HDIM];
__device__ __nv_bfloat16 g_khi[(size_t)BATCH * NH * SEQ * HDIM];
__device__ __nv_bfloat16 g_klo[(size_t)BATCH * NH * SEQ * HDIM];
__device__ __nv_bfloat16 g_vhi[(size_t)BATCH * NH * SEQ * HDIM];
__device__ __nv_bfloat16 g_vlo[(size_t)BATCH * NH * SEQ * HDIM];

// ---------------- PTX helpers (sm_80-era, compute_103-safe) ----------------
__device__ __forceinline__ uint32_t smem_u32(const void* p) {
    uint32_t a;
    asm("{ .reg .u64 t; cvta.to.shared.u64 t, %1; cvt.u32.u64 %0, t; }" : "=r"(a) : "l"(p));
    return a;
}
__device__ __forceinline__ void cp16(uint32_t s, const void* g) {
    asm volatile("cp.async.cg.shared.global [%0], [%1], 16;" :: "r"(s), "l"(g) : "memory");
}
__device__ __forceinline__ void ldsm4(uint32_t* r, uint32_t addr) {
    asm volatile("ldmatrix.sync.aligned.m8n8.x4.shared.b16 {%0,%1,%2,%3}, [%4];"
                 : "=r"(r[0]), "=r"(r[1]), "=r"(r[2]), "=r"(r[3]) : "r"(addr));
}
__device__ __forceinline__ void mma_bf16(float* d, const uint32_t* a, uint32_t b0, uint32_t b1) {
    asm volatile("mma.sync.aligned.m16n8k16.row.col.f32.bf16.bf16.f32 "
                 "{%0,%1,%2,%3}, {%4,%5,%6,%7}, {%8,%9}, {%0,%1,%2,%3};"
                 : "+f"(d[0]), "+f"(d[1]), "+f"(d[2]), "+f"(d[3])
                 : "r"(a[0]), "r"(a[1]), "r"(a[2]), "r"(a[3]), "r"(b0), "r"(b1));
}
// pack (lo, hi) into bf16x2 reg: first PTX src becomes HIGH half
__device__ __forceinline__ uint32_t pack_bf16(float lo, float hi) {
    uint32_t r;
    asm("cvt.rn.bf16x2.f32 %0, %1, %2;" : "=r"(r) : "f"(hi), "f"(lo));
    return r;
}
// fast 2^t on FMA pipe (no MUFU); t clamped at -120 (exp of masked -> ~0)
__device__ __forceinline__ float exp2p(float t) {
    t = fmaxf(t, -120.f);
    float n = floorf(t);
    float f = t - n;
    float p = fmaf(f, 1.3333558e-4f, 1.3400431e-3f);
    p = fmaf(f, p, 9.6181291e-3f);
    p = fmaf(f, p, 5.5504109e-2f);
    p = fmaf(f, p, 2.4022651e-1f);
    p = fmaf(f, p, 6.9314718e-1f);
    p = fmaf(f, p, 1.0f);
    return p * __int_as_float(((int)n + 127) << 23);
}

struct alignas(8) bh4 { __nv_bfloat16 h[4]; };

// ============================================================================
// Split prepass 1: activations  src fp32 [M][4096] -> dst bf16 [M][12288]
// ============================================================================
__global__ __launch_bounds__(256) void split_act_kernel(const float* __restrict__ src,
                                                        __nv_bfloat16* __restrict__ dst) {
    size_t i = (size_t)blockIdx.x * 256 + threadIdx.x;
    int row = (int)(i >> 10);
    int kc  = (int)(i & 1023);
    float4 v = ((const float4*)src)[i];
    bh4 hi, lo;
    hi.h[0] = __float2bfloat16(v.x); lo.h[0] = __float2bfloat16(v.x - __bfloat162float(hi.h[0]));
    hi.h[1] = __float2bfloat16(v.y); lo.h[1] = __float2bfloat16(v.y - __bfloat162float(hi.h[1]));
    hi.h[2] = __float2bfloat16(v.z); lo.h[2] = __float2bfloat16(v.z - __bfloat162float(hi.h[2]));
    hi.h[3] = __float2bfloat16(v.w); lo.h[3] = __float2bfloat16(v.w - __bfloat162float(hi.h[3]));
    __nv_bfloat16* d = dst + (size_t)row * KSPLIT + kc * 4;
    *(bh4*)(d)        = hi;
    *(bh4*)(d + 4096) = hi;
    *(bh4*)(d + 8192) = lo;
}

// ============================================================================
// Split prepass 2: weights  src fp32 [K=4096][N] -> dst bf16 [N][12288]
// ============================================================================
__global__ __launch_bounds__(256) void split_w_kernel(const float* __restrict__ src,
                                                      __nv_bfloat16* __restrict__ dst,
                                                      int N) {
    __shared__ float t[32][33];
    int n0 = blockIdx.x * 32, k0 = blockIdx.y * 32;
    int tx = threadIdx.x & 31, ty = threadIdx.x >> 5;
#pragma unroll
    for (int i = 0; i < 4; i++)
        t[ty + i * 8][tx] = src[(size_t)(k0 + ty + i * 8) * N + n0 + tx];
    __syncthreads();
#pragma unroll
    for (int i = 0; i < 4; i++) {
        int n = n0 + ty + i * 8;
        int k = k0 + tx;
        float x = t[tx][ty + i * 8];
        __nv_bfloat16 hi = __float2bfloat16(x);
        __nv_bfloat16 lo = __float2bfloat16(x - __bfloat162float(hi));
        __nv_bfloat16* d = dst + (size_t)n * KSPLIT;
        d[k]        = hi;
        d[4096 + k] = lo;
        d[8192 + k] = hi;
    }
}

// ============================================================================
// bf16 tensor-core GEMM (unchanged from R3)
// ============================================================================
#define GSTAGES   4
#define GROW_B    80
#define GTILE_B   (128 * GROW_B)
#define GSTAGE_B  (2 * GTILE_B)
#define GSMEM_B   (GSTAGES * GSTAGE_B)

__global__ __launch_bounds__(256, 2) void gemm_bf16_kernel(const __nv_bfloat16* __restrict__ A,
                                                           const __nv_bfloat16* __restrict__ B,
                                                           float* __restrict__ C, int N) {
    extern __shared__ char sm[];
    const int KT  = KSPLIT;
    const int NT  = KT / 32;
    const int tid  = threadIdx.x;
    const int lane = tid & 31;
    const int wid  = tid >> 5;
    const int wm   = wid & 3;
    const int wn   = wid >> 2;

    const int tiles_n = N >> 7;
    int bid  = blockIdx.x + blockIdx.y * gridDim.x;
    int band = bid / (8 * tiles_n);
    int rem  = bid % (8 * tiles_n);
    const int mt = band * 8 + (rem & 7);
    const int nt = rem >> 3;
    const int row0 = mt * 128, col0 = nt * 128;

    const __nv_bfloat16* Ab = A + (size_t)row0 * KT;
    const __nv_bfloat16* Bb = B + (size_t)col0 * KT;
    const uint32_t smb = smem_u32(sm);

    auto load_stage = [&](int s, int kt) {
        uint32_t sA = smb + s * GSTAGE_B;
        const __nv_bfloat16* ga = Ab + kt * 32;
        const __nv_bfloat16* gb = Bb + kt * 32;
#pragma unroll
        for (int i = 0; i < 2; i++) {
            int c   = tid + i * 256;
            int row = c >> 2;
            int kc  = c & 3;
            cp16(sA + row * GROW_B + kc * 16,            ga + (size_t)row * KT + kc * 8);
            cp16(sA + GTILE_B + row * GROW_B + kc * 16,  gb + (size_t)row * KT + kc * 8);
        }
    };

    load_stage(0, 0); asm volatile("cp.async.commit_group;" ::: "memory");
    load_stage(1, 1); asm volatile("cp.async.commit_group;" ::: "memory");
    load_stage(2, 2); asm volatile("cp.async.commit_group;" ::: "memory");

    float acc[2][8][4];
#pragma unroll
    for (int i = 0; i < 2; i++)
#pragma unroll
        for (int j = 0; j < 8; j++)
#pragma unroll
            for (int q = 0; q < 4; q++) acc[i][j][q] = 0.f;

    const int a_row = lane & 15;
    const int a_col = (lane >> 4) * 8;
    const int b_nl  = (lane & 7) + ((lane >> 4) & 1) * 8;
    const int b_kl  = ((lane >> 3) & 1) * 8;

    for (int kt = 0; kt < NT; kt++) {
        asm volatile("cp.async.wait_group 2;" ::: "memory");
        __syncthreads();
        const int s = kt & 3;
        const uint32_t aB = smb + s * GSTAGE_B;
        const uint32_t bB = aB + GTILE_B;

#pragma unroll
        for (int ks = 0; ks < 2; ks++) {
            uint32_t afrag[2][4];
#pragma unroll
            for (int mf = 0; mf < 2; mf++)
                ldsm4(afrag[mf], aB + (uint32_t)((wm * 32 + mf * 16 + a_row) * GROW_B
                                                 + (ks * 16 + a_col) * 2));
#pragma unroll
            for (int nf2 = 0; nf2 < 4; nf2++) {
                uint32_t bfrag[4];
                ldsm4(bfrag, bB + (uint32_t)((wn * 64 + nf2 * 16 + b_nl) * GROW_B
                                             + (ks * 16 + b_kl) * 2));
#pragma unroll
                for (int mf = 0; mf < 2; mf++) {
                    mma_bf16(acc[mf][nf2 * 2],     afrag[mf], bfrag[0], bfrag[1]);
                    mma_bf16(acc[mf][nf2 * 2 + 1], afrag[mf], bfrag[2], bfrag[3]);
                }
            }
        }
        if (kt + 3 < NT) load_stage((kt + 3) & 3, kt + 3);
        asm volatile("cp.async.commit_group;" ::: "memory");
    }

#pragma unroll
    for (int mf = 0; mf < 2; mf++)
#pragma unroll
        for (int nf = 0; nf < 8; nf++) {
            int r  = row0 + wm * 32 + mf * 16 + (lane >> 2);
            int cc = col0 + wn * 64 + nf * 8 + (lane & 3) * 2;
            *(float2*)&C[(size_t)r * N + cc]       = make_float2(acc[mf][nf][0], acc[mf][nf][1]);
            *(float2*)&C[(size_t)(r + 8) * N + cc] = make_float2(acc[mf][nf][2], acc[mf][nf][3]);
        }
}

// ============================================================================
// NeoX RoPE in-place on q and k of g_qkv.
// ============================================================================
__global__ void rope_kernel(const int* __restrict__ positions) {
    int idx = blockIdx.x * blockDim.x + threadIdx.x;
    int j  = idx & 31;
    int h  = (idx >> 5) & 31;
    int bs = idx >> 10;

    float pos = (float)positions[bs];
    float inv = powf(10000.0f, -(float)j * (1.0f / 32.0f));
    float sn, cs;
    sincosf(pos * inv, &sn, &cs);

    size_t base = (size_t)bs * QKVN + (size_t)h * HDIM;
    float x1 = g_qkv[base + j], x2 = g_qkv[base + 32 + j];
    g_qkv[base + j]      = x1 * cs - x2 * sn;
    g_qkv[base + 32 + j] = x2 * cs + x1 * sn;
    size_t kb = base + HID;
    x1 = g_qkv[kb + j]; x2 = g_qkv[kb + 32 + j];
    g_qkv[kb + j]      = x1 * cs - x2 * sn;
    g_qkv[kb + 32 + j] = x2 * cs + x1 * sn;
}

// ============================================================================
// Flash prepass A: split q (prescaled by 1/sqrt(d)*log2e) and k to bf16 hi/lo,
// layout [bh][s][d]
// ============================================================================
#define QSC (0.08838834764831845f * 1.4426950408889634f)

__global__ __launch_bounds__(256) void split_qk_kernel() {
    size_t i = (size_t)blockIdx.x * 256 + threadIdx.x;   // over MROWS*1024 float4
    int bs = (int)(i >> 10);
    int e  = ((int)(i & 1023)) << 2;                     // element in [0,4096)
    int h  = e >> 7;
    int d  = e & 127;
    int b  = bs >> 11;
    int s  = bs & 2047;
    size_t dst = ((size_t)(b * NH + h) * SEQ + s) * HDIM + d;

    float4 q = *(const float4*)&g_qkv[(size_t)bs * QKVN + e];
    bh4 hi, lo;
    float x;
    x = q.x * QSC; hi.h[0] = __float2bfloat16(x); lo.h[0] = __float2bfloat16(x - __bfloat162float(hi.h[0]));
    x = q.y * QSC; hi.h[1] = __float2bfloat16(x); lo.h[1] = __float2bfloat16(x - __bfloat162float(hi.h[1]));
    x = q.z * QSC; hi.h[2] = __float2bfloat16(x); lo.h[2] = __float2bfloat16(x - __bfloat162float(hi.h[2]));
    x = q.w * QSC; hi.h[3] = __float2bfloat16(x); lo.h[3] = __float2bfloat16(x - __bfloat162float(hi.h[3]));
    *(bh4*)&g_qhi[dst] = hi;
    *(bh4*)&g_qlo[dst] = lo;

    float4 k = *(const float4*)&g_qkv[(size_t)bs * QKVN + HID + e];
    x = k.x; hi.h[0] = __float2bfloat16(x); lo.h[0] = __float2bfloat16(x - __bfloat162float(hi.h[0]));
    x = k.y; hi.h[1] = __float2bfloat16(x); lo.h[1] = __float2bfloat16(x - __bfloat162float(hi.h[1]));
    x = k.z; hi.h[2] = __float2bfloat16(x); lo.h[2] = __float2bfloat16(x - __bfloat162float(hi.h[2]));
    x = k.w; hi.h[3] = __float2bfloat16(x); lo.h[3] = __float2bfloat16(x - __bfloat162float(hi.h[3]));
    *(bh4*)&g_khi[dst] = hi;
    *(bh4*)&g_klo[dst] = lo;
}

// ============================================================================
// Flash prepass B: split v to bf16 hi/lo TRANSPOSED, layout [bh][d][s]
// ============================================================================
__global__ __launch_bounds__(256) void split_v_kernel() {
    __shared__ float t[32][33];
    int s0 = blockIdx.x * 32;
    int d0 = blockIdx.y * 32;
    int bh = blockIdx.z;
    int b  = bh >> 5, h = bh & 31;
    int tx = threadIdx.x & 31, ty = threadIdx.x >> 5;
#pragma unroll
    for (int i = 0; i < 4; i++)
        t[ty + i * 8][tx] = g_qkv[((size_t)(b * SEQ + s0 + ty + i * 8)) * QKVN
                                  + 2 * HID + h * HDIM + d0 + tx];
    __syncthreads();
#pragma unroll
    for (int i = 0; i < 4; i++) {
        int d = d0 + ty + i * 8;
        float x = t[tx][ty + i * 8];
        __nv_bfloat16 hi = __float2bfloat16(x);
        __nv_bfloat16 lo = __float2bfloat16(x - __bfloat162float(hi));
        size_t dst = ((size_t)bh * HDIM + d) * SEQ + s0 + tx;
        g_vhi[dst] = hi;
        g_vlo[dst] = lo;
    }
}

// ============================================================================
// Tensor-core flash attention (exact via bf16 hi/lo 3-term split), causal.
// CTA: 128 q-rows x one (b,h). 8 warps x 16 rows. KV tile = 64 keys.
// ============================================================================
#define FQ   128
#define FK   64
#define QROWB 272   // Q/K smem row stride bytes (136 bf16)
#define VROWB 144   // V smem row stride bytes (72 bf16)
#define OQH  0
#define OQL  34816
#define OST  69632
#define FKL  17408
#define FVH  34816
#define FVL  53248
#define FSTAGE 71680
#define FSMEM (OST + 2 * FSTAGE)   // 212992

__global__ __launch_bounds__(256, 1) void flash_tc_kernel() {
    extern __shared__ char sm[];
    const uint32_t smb = smem_u32(sm);
    const int tid  = threadIdx.x;
    const int lane = tid & 31;
    const int w    = tid >> 5;
    const int qt   = gridDim.x - 1 - blockIdx.x;   // big tiles first
    const int bh   = blockIdx.y;
    const int ntiles = 2 * qt + 2;

    // ---- Q load (part of group 0) ----
    {
        size_t qoff = ((size_t)bh * SEQ + (size_t)qt * FQ) * HDIM;
#pragma unroll
        for (int i = tid; i < 2048; i += 256) {
            int r = i >> 4, c = i & 15;
            cp16(smb + OQH + r * QROWB + c * 16, g_qhi + qoff + (size_t)r * HDIM + c * 8);
            cp16(smb + OQL + r * QROWB + c * 16, g_qlo + qoff + (size_t)r * HDIM + c * 8);
        }
    }

    auto load_kv = [&](int st, int kt) {
        uint32_t sb = smb + OST + st * FSTAGE;
        size_t koff = ((size_t)bh * SEQ + (size_t)kt * FK) * HDIM;
#pragma unroll
        for (int i = tid; i < 1024; i += 256) {
            int r = i >> 4, c = i & 15;
            cp16(sb + r * QROWB + c * 16,       g_khi + koff + (size_t)r * HDIM + c * 8);
            cp16(sb + FKL + r * QROWB + c * 16, g_klo + koff + (size_t)r * HDIM + c * 8);
        }
        size_t voff = (size_t)bh * HDIM * SEQ + (size_t)kt * FK;
#pragma unroll
        for (int i = tid; i < 1024; i += 256) {
            int d = i >> 3, c = i & 7;
            cp16(sb + FVH + d * VROWB + c * 16, g_vhi + voff + (size_t)d * SEQ + c * 8);
            cp16(sb + FVL + d * VROWB + c * 16, g_vlo + voff + (size_t)d * SEQ + c * 8);
        }
    };

    load_kv(0, 0);
    asm volatile("cp.async.commit_group;" ::: "memory");

    float o[16][4];
#pragma unroll
    for (int i = 0; i < 16; i++)
#pragma unroll
        for (int j = 0; j < 4; j++) o[i][j] = 0.f;
    float m0 = -CUDART_INF_F, m1 = -CUDART_INF_F, l0 = 0.f, l1 = 0.f;

    const int a_row = lane & 15;
    const int a_col = (lane >> 4) * 8;
    const int b_nl  = (lane & 7) + ((lane >> 4) & 1) * 8;
    const int b_kl  = ((lane >> 3) & 1) * 8;
    const int qrow0 = qt * FQ + w * 16 + (lane >> 2);   // this thread's row (and +8)

    for (int kt = 0; kt < ntiles; kt++) {
        if (kt + 1 < ntiles) load_kv((kt + 1) & 1, kt + 1);
        asm volatile("cp.async.commit_group;" ::: "memory");
        asm volatile("cp.async.wait_group 1;" ::: "memory");
        __syncthreads();

        const uint32_t kb = smb + OST + (kt & 1) * FSTAGE;
        const uint32_t vb = kb + FVH;

        // ---- S = Q K^T (3-term split) ----
        float s[8][4];
#pragma unroll
        for (int i = 0; i < 8; i++)
#pragma unroll
            for (int j = 0; j < 4; j++) s[i][j] = 0.f;

#pragma unroll
        for (int ks = 0; ks < 8; ks++) {
            uint32_t qh[4], ql[4];
            uint32_t qaddr = smb + OQH + (uint32_t)((w * 16 + a_row) * QROWB + (ks * 16 + a_col) * 2);
            ldsm4(qh, qaddr);
            ldsm4(ql, qaddr + (OQL - OQH));
#pragma unroll
            for (int nt2 = 0; nt2 < 4; nt2++) {
                uint32_t kh[4], kl[4];
                uint32_t kaddr = kb + (uint32_t)((nt2 * 16 + b_nl) * QROWB + (ks * 16 + b_kl) * 2);
                ldsm4(kh, kaddr);
                ldsm4(kl, kaddr + FKL);
                mma_bf16(s[nt2 * 2],     qh, kh[0], kh[1]);
                mma_bf16(s[nt2 * 2 + 1], qh, kh[2], kh[3]);
                mma_bf16(s[nt2 * 2],     qh, kl[0], kl[1]);
                mma_bf16(s[nt2 * 2 + 1], qh, kl[2], kl[3]);
                mma_bf16(s[nt2 * 2],     ql, kh[0], kh[1]);
                mma_bf16(s[nt2 * 2 + 1], ql, kh[2], kh[3]);
            }
        }

        // ---- causal mask (diagonal tiles only) ----
        if (kt * FK + FK - 1 > qt * FQ + w * 16) {
#pragma unroll
            for (int nt = 0; nt < 8; nt++) {
                int key = kt * FK + nt * 8 + (lane & 3) * 2;
                if (key     > qrow0)     s[nt][0] = -CUDART_INF_F;
                if (key + 1 > qrow0)     s[nt][1] = -CUDART_INF_F;
                if (key     > qrow0 + 8) s[nt][2] = -CUDART_INF_F;
                if (key + 1 > qrow0 + 8) s[nt][3] = -CUDART_INF_F;
            }
        }

        // ---- online softmax (log2 domain; scale folded into Q) ----
        float mx0 = -CUDART_INF_F, mx1 = -CUDART_INF_F;
#pragma unroll
        for (int nt = 0; nt < 8; nt++) {
            mx0 = fmaxf(mx0, fmaxf(s[nt][0], s[nt][1]));
            mx1 = fmaxf(mx1, fmaxf(s[nt][2], s[nt][3]));
        }
        mx0 = fmaxf(mx0, __shfl_xor_sync(0xffffffffu, mx0, 1));
        mx0 = fmaxf(mx0, __shfl_xor_sync(0xffffffffu, mx0, 2));
        mx1 = fmaxf(mx1, __shfl_xor_sync(0xffffffffu, mx1, 1));
        mx1 = fmaxf(mx1, __shfl_xor_sync(0xffffffffu, mx1, 2));
        float mn0 = fmaxf(m0, mx0), mn1 = fmaxf(m1, mx1);
        float al0 = exp2p(m0 - mn0), al1 = exp2p(m1 - mn1);
        m0 = mn0; m1 = mn1;

        float sum0 = 0.f, sum1 = 0.f;
#pragma unroll
        for (int nt = 0; nt < 8; nt++) {
            s[nt][0] = exp2p(s[nt][0] - mn0); sum0 += s[nt][0];
            s[nt][1] = exp2p(s[nt][1] - mn0); sum0 += s[nt][1];
            s[nt][2] = exp2p(s[nt][2] - mn1); sum1 += s[nt][2];
            s[nt][3] = exp2p(s[nt][3] - mn1); sum1 += s[nt][3];
        }
        sum0 += __shfl_xor_sync(0xffffffffu, sum0, 1);
        sum0 += __shfl_xor_sync(0xffffffffu, sum0, 2);
        sum1 += __shfl_xor_sync(0xffffffffu, sum1, 1);
        sum1 += __shfl_xor_sync(0xffffffffu, sum1, 2);
        l0 = l0 * al0 + sum0;
        l1 = l1 * al1 + sum1;

#pragma unroll
        for (int nt = 0; nt < 16; nt++) {
            o[nt][0] *= al0; o[nt][1] *= al0;
            o[nt][2] *= al1; o[nt][3] *= al1;
        }

        // ---- O += P V (3-term split; P fragments direct from registers) ----
#pragma unroll
        for (int g = 0; g < 4; g++) {
            float h00 = __bfloat162float(__float2bfloat16(s[2*g][0]));
            float h01 = __bfloat162float(__float2bfloat16(s[2*g][1]));
            float h02 = __bfloat162float(__float2bfloat16(s[2*g][2]));
            float h03 = __bfloat162float(__float2bfloat16(s[2*g][3]));
            float h10 = __bfloat162float(__float2bfloat16(s[2*g+1][0]));
            float h11 = __bfloat162float(__float2bfloat16(s[2*g+1][1]));
            float h12 = __bfloat162float(__float2bfloat16(s[2*g+1][2]));
            float h13 = __bfloat162float(__float2bfloat16(s[2*g+1][3]));
            uint32_t phi[4], plo[4];
            phi[0] = pack_bf16(h00, h01);
            phi[1] = pack_bf16(h02, h03);
            phi[2] = pack_bf16(h10, h11);
            phi[3] = pack_bf16(h12, h13);
            plo[0] = pack_bf16(s[2*g][0] - h00,   s[2*g][1] - h01);
            plo[1] = pack_bf16(s[2*g][2] - h02,   s[2*g][3] - h03);
            plo[2] = pack_bf16(s[2*g+1][0] - h10, s[2*g+1][1] - h11);
            plo[3] = pack_bf16(s[2*g+1][2] - h12, s[2*g+1][3] - h13);

#pragma unroll
            for (int dt2 = 0; dt2 < 8; dt2++) {
                uint32_t vh[4], vl[4];
                uint32_t vaddr = vb + (uint32_t)((dt2 * 16 + b_nl) * VROWB + (g * 16 + b_kl) * 2);
                ldsm4(vh, vaddr);
                ldsm4(vl, vaddr + (FVL - FVH));
                mma_bf16(o[dt2 * 2],     phi, vh[0], vh[1]);
                mma_bf16(o[dt2 * 2 + 1], phi, vh[2], vh[3]);
                mma_bf16(o[dt2 * 2],     phi, vl[0], vl[1]);
                mma_bf16(o[dt2 * 2 + 1], phi, vl[2], vl[3]);
                mma_bf16(o[dt2 * 2],     plo, vh[0], vh[1]);
                mma_bf16(o[dt2 * 2 + 1], plo, vh[2], vh[3]);
            }
        }
        __syncthreads();   // all reads of this stage done before it is reloaded
    }

    // ---- epilogue ----
    const float invl0 = 1.0f / l0;
    const float invl1 = 1.0f / l1;
    const int b = bh >> 5, h = bh & 31;
    const size_t r0 = (size_t)(b * SEQ + qt * FQ + w * 16 + (lane >> 2));
#pragma unroll
    for (int nt = 0; nt < 16; nt++) {
        size_t cbase = h * HDIM + nt * 8 + (lane & 3) * 2;
        *(float2*)&g_attn[r0 * HID + cbase] =
            make_float2(o[nt][0] * invl0, o[nt][1] * invl0);
        *(float2*)&g_attn[(r0 + 8) * HID + cbase] =
            make_float2(o[nt][2] * invl1, o[nt][3] * invl1);
    }
}

// ============================================================================
extern "C" void kernel_launch(void* const* d_in, const int* in_sizes, int n_in,
                              void* d_out, int out_size) {
    const float* hidden    = (const float*)d_in[0];
    const int*   positions = (const int*)d_in[1];
    const float* Wqkv      = (const float*)d_in[2];
    const float* Wout      = (const float*)d_in[3];
    float*       out       = (float*)d_out;

    float*         qkv;  cudaGetSymbolAddress((void**)&qkv,  g_qkv);
    float*         attn; cudaGetSymbolAddress((void**)&attn, g_attn);
    __nv_bfloat16* A2;   cudaGetSymbolAddress((void**)&A2,   g_A2);
    __nv_bfloat16* B2;   cudaGetSymbolAddress((void**)&B2,   g_B2);

    static bool attr_done = false;
    if (!attr_done) {
        cudaFuncSetAttribute(gemm_bf16_kernel, cudaFuncAttributeMaxDynamicSharedMemorySize, GSMEM_B);
        cudaFuncSetAttribute(flash_tc_kernel, cudaFuncAttributeMaxDynamicSharedMemorySize, FSMEM);
        attr_done = true;
    }

    // 1) split activations + weights
    split_act_kernel<<<(MROWS * (HID / 4)) / 256, 256>>>(hidden, A2);
    split_w_kernel<<<dim3(QKVN / 32, HID / 32), 256>>>(Wqkv, B2, QKVN);

    // 2) QKV projection (tensor cores, exact via 3-term split)
    gemm_bf16_kernel<<<dim3(QKVN / 128, MROWS / 128), 256, GSMEM_B>>>(A2, B2, qkv, QKVN);

    // 3) RoPE
    rope_kernel<<<(MROWS * NH * 32) / 256, 256>>>(positions);

    // 4) split q/k/v into flash bf16 hi/lo operands
    split_qk_kernel<<<(MROWS * (HID / 4)) / 256, 256>>>();
    split_v_kernel<<<dim3(SEQ / 32, HDIM / 32, BATCH * NH), 256>>>();

    // 5) tensor-core causal flash attention
    flash_tc_kernel<<<dim3(SEQ / FQ, BATCH * NH), 256, FSMEM>>>();

    // 6) output projection
    split_act_kernel<<<(MROWS * (HID / 4)) / 256, 256>>>(attn, A2);
    split_w_kernel<<<dim3(HID / 32, HID / 32), 256>>>(Wout, B2, HID);
    gemm_bf16_kernel<<<dim3(HID / 128, MROWS / 128), 256, GSMEM_B>>>(A2, B2, out, HID);
}